// round 1
// baseline (speedup 1.0000x reference)
#include <cuda_runtime.h>
#include <cstddef>

#define N_NODES 50000
#define N_EDGES 500000
#define D 128
#define H1 256

// ---------------- scratch (static device globals; no allocation) ----------------
__device__ float d_h  [N_NODES * D];
__device__ float d_h2 [N_NODES * D];
__device__ float d_hid[(size_t)N_EDGES * H1];      // 512 MB hidden scratch
__device__ float d_ep [(size_t)N_EDGES * D];       // edge_p features (computed once)
__device__ float d_ec [(size_t)N_EDGES * D];       // edge_c features
__device__ float d_sp [N_NODES * D];
__device__ float d_sc [N_NODES * D];
__device__ float d_cp [N_NODES];
__device__ float d_cc [N_NODES];

// ---------------- generic tiled SGEMM: out = f(A[M,K] @ W[K,Nn] + bias) ----------------
// mode 0: out[r*Nn+c]       = relu(v)
// mode 1: atomicAdd(&out[sidx[r]*Nn+c], relu(v))          (fused segment-sum scatter)
// mode 2: out[r*Nn+c]       = relu(res[r*Nn+c] + relu(v)) (residual + outer relu)
__global__ __launch_bounds__(256) void gemm_plain(
    const float* __restrict__ A, int M, int K,
    const float* __restrict__ W, int Nn,
    const float* __restrict__ bias,
    float* __restrict__ out,
    int mode, const int* __restrict__ sidx, const float* __restrict__ res)
{
    __shared__ float As[16][64];
    __shared__ float Bs[16][64];
    const int bm = blockIdx.y * 64;
    const int bn = blockIdx.x * 64;
    const int tid = threadIdx.x;
    const int tx = tid & 15, ty = tid >> 4;
    float acc[4][4] = {};

    for (int k0 = 0; k0 < K; k0 += 16) {
#pragma unroll
        for (int r = 0; r < 4; r++) {
            int e = tid + 256 * r;
            int row = e >> 4, col = e & 15;
            int gr = bm + row;
            As[col][row] = (gr < M) ? A[(size_t)gr * K + k0 + col] : 0.f;
        }
#pragma unroll
        for (int r = 0; r < 4; r++) {
            int e = tid + 256 * r;
            int row = e >> 6, col = e & 63;
            Bs[row][col] = W[(size_t)(k0 + row) * Nn + bn + col];
        }
        __syncthreads();
#pragma unroll
        for (int kk = 0; kk < 16; kk++) {
            float a[4], b[4];
#pragma unroll
            for (int i = 0; i < 4; i++) a[i] = As[kk][ty * 4 + i];
#pragma unroll
            for (int j = 0; j < 4; j++) b[j] = Bs[kk][tx * 4 + j];
#pragma unroll
            for (int i = 0; i < 4; i++)
#pragma unroll
                for (int j = 0; j < 4; j++)
                    acc[i][j] = fmaf(a[i], b[j], acc[i][j]);
        }
        __syncthreads();
    }

#pragma unroll
    for (int i = 0; i < 4; i++) {
        int gr = bm + ty * 4 + i;
        if (gr >= M) continue;
#pragma unroll
        for (int j = 0; j < 4; j++) {
            int gc = bn + tx * 4 + j;
            float v = fmaxf(acc[i][j] + bias[gc], 0.f);
            if (mode == 0)      out[(size_t)gr * Nn + gc] = v;
            else if (mode == 1) atomicAdd(&out[(size_t)sidx[gr] * Nn + gc], v);
            else                out[(size_t)gr * Nn + gc] =
                                    fmaxf(res[(size_t)gr * Nn + gc] + v, 0.f);
        }
    }
}

// ---------------- GEMM with on-the-fly 3-way concat + gather A (K = 384 fixed) ----
// A(row, k) = k<128 ? s0[(i0?i0[row]:row)*128+k]
//           : k<256 ? s1[(i1?i1[row]:row)*128+k-128]
//           :         s2[row*128 + k-256]
// out[M, 256] = relu(A @ W + bias)
__global__ __launch_bounds__(256) void gemm_cat3(
    const float* __restrict__ s0, const int* __restrict__ i0,
    const float* __restrict__ s1, const int* __restrict__ i1,
    const float* __restrict__ s2,
    int M,
    const float* __restrict__ W,     // [384, 256]
    const float* __restrict__ bias,  // [256]
    float* __restrict__ out)         // [M, 256]
{
    __shared__ float As[16][64];
    __shared__ float Bs[16][64];
    const int bm = blockIdx.y * 64;
    const int bn = blockIdx.x * 64;
    const int tid = threadIdx.x;
    const int tx = tid & 15, ty = tid >> 4;
    float acc[4][4] = {};

    for (int k0 = 0; k0 < 384; k0 += 16) {
        const float* src; const int* idx; int koff;
        if (k0 < 128)      { src = s0; idx = i0; koff = k0; }
        else if (k0 < 256) { src = s1; idx = i1; koff = k0 - 128; }
        else               { src = s2; idx = nullptr; koff = k0 - 256; }
#pragma unroll
        for (int r = 0; r < 4; r++) {
            int e = tid + 256 * r;
            int row = e >> 4, col = e & 15;
            int gr = bm + row;
            float v = 0.f;
            if (gr < M) {
                int rr = idx ? idx[gr] : gr;
                v = src[(size_t)rr * 128 + koff + col];
            }
            As[col][row] = v;
        }
#pragma unroll
        for (int r = 0; r < 4; r++) {
            int e = tid + 256 * r;
            int row = e >> 6, col = e & 63;
            Bs[row][col] = W[(size_t)(k0 + row) * 256 + bn + col];
        }
        __syncthreads();
#pragma unroll
        for (int kk = 0; kk < 16; kk++) {
            float a[4], b[4];
#pragma unroll
            for (int i = 0; i < 4; i++) a[i] = As[kk][ty * 4 + i];
#pragma unroll
            for (int j = 0; j < 4; j++) b[j] = Bs[kk][tx * 4 + j];
#pragma unroll
            for (int i = 0; i < 4; i++)
#pragma unroll
                for (int j = 0; j < 4; j++)
                    acc[i][j] = fmaf(a[i], b[j], acc[i][j]);
        }
        __syncthreads();
    }

#pragma unroll
    for (int i = 0; i < 4; i++) {
        int gr = bm + ty * 4 + i;
        if (gr >= M) continue;
#pragma unroll
        for (int j = 0; j < 4; j++) {
            int gc = bn + tx * 4 + j;
            out[(size_t)gr * 256 + gc] = fmaxf(acc[i][j] + bias[gc], 0.f);
        }
    }
}

// ---------------- small elementwise kernels ----------------
// MLP_E first layer: din=1 -> hid[e,j] = relu(ind[e]*w1[j] + b1[j])
__global__ void edge_hidden(const float* __restrict__ ind,
                            const float* __restrict__ w1,
                            const float* __restrict__ b1,
                            float* __restrict__ hid)
{
    size_t i = (size_t)blockIdx.x * blockDim.x + threadIdx.x;
    if (i >= (size_t)N_EDGES * H1) return;
    int j = (int)(i & (H1 - 1));
    int e = (int)(i >> 8);
    hid[i] = fmaxf(ind[e] * w1[j] + b1[j], 0.f);
}

__global__ void count_edges(const int* __restrict__ pn, const int* __restrict__ cn,
                            float* __restrict__ cp, float* __restrict__ cc)
{
    int e = blockIdx.x * blockDim.x + threadIdx.x;
    if (e < N_EDGES) {
        atomicAdd(&cp[pn[e]], 1.f);
        atomicAdd(&cc[cn[e]], 1.f);
    }
}

// s_p = s_p / max(cnt_p,1) + p_mask*start ; s_c = s_c / max(cnt_c,1) + c_mask*end
__global__ void finalize_s(float* __restrict__ sp, float* __restrict__ sc,
                           const float* __restrict__ cp, const float* __restrict__ cc,
                           const float* __restrict__ pm, const float* __restrict__ cm,
                           const float* __restrict__ st, const float* __restrict__ et)
{
    int i = blockIdx.x * blockDim.x + threadIdx.x;
    if (i >= N_NODES * D) return;
    int n = i >> 7, d = i & 127;
    sp[i] = sp[i] / fmaxf(cp[n], 1.f) + pm[n] * st[d];
    sc[i] = sc[i] / fmaxf(cc[n], 1.f) + cm[n] * et[d];
}

// ---------------- host ----------------
static inline dim3 gemm_grid(int M, int Nn) { return dim3(Nn / 64, (M + 63) / 64); }

extern "C" void kernel_launch(void* const* d_in, const int* in_sizes, int n_in,
                              void* d_out, int out_size)
{
    (void)in_sizes; (void)n_in; (void)out_size;
    const float* batch_token = (const float*)d_in[0];
    const int*   e_p_node    = (const int*)  d_in[1];
    const int*   e_c_node    = (const int*)  d_in[2];
    const float* e_p_ind     = (const float*)d_in[3];
    const float* e_c_ind     = (const float*)d_in[4];
    const float* p_mask      = (const float*)d_in[5];
    const float* c_mask      = (const float*)d_in[6];
    const float* start_tok   = (const float*)d_in[7];
    const float* end_tok     = (const float*)d_in[8];
    const float* Wt[20];
    for (int i = 0; i < 20; i++) Wt[i] = (const float*)d_in[9 + i];
    // V: 0-3, E: 4-7, P: 8-11, C: 12-15, A: 16-19
    const float *Vw1=Wt[0],*Vb1=Wt[1],*Vw2=Wt[2],*Vb2=Wt[3];
    const float *Ew1=Wt[4],*Eb1=Wt[5],*Ew2=Wt[6],*Eb2=Wt[7];
    const float *Pw1=Wt[8],*Pb1=Wt[9],*Pw2=Wt[10],*Pb2=Wt[11];
    const float *Cw1=Wt[12],*Cb1=Wt[13],*Cw2=Wt[14],*Cb2=Wt[15];
    const float *Aw1=Wt[16],*Ab1=Wt[17],*Aw2=Wt[18],*Ab2=Wt[19];

    float *g_h, *g_h2, *g_hid, *g_ep, *g_ec, *g_sp, *g_sc, *g_cp, *g_cc;
    cudaGetSymbolAddress((void**)&g_h,   d_h);
    cudaGetSymbolAddress((void**)&g_h2,  d_h2);
    cudaGetSymbolAddress((void**)&g_hid, d_hid);
    cudaGetSymbolAddress((void**)&g_ep,  d_ep);
    cudaGetSymbolAddress((void**)&g_ec,  d_ec);
    cudaGetSymbolAddress((void**)&g_sp,  d_sp);
    cudaGetSymbolAddress((void**)&g_sc,  d_sc);
    cudaGetSymbolAddress((void**)&g_cp,  d_cp);
    cudaGetSymbolAddress((void**)&g_cc,  d_cc);

    cudaStream_t s = 0;

    // ---- edge counts ----
    cudaMemsetAsync(g_cp, 0, N_NODES * sizeof(float), s);
    cudaMemsetAsync(g_cc, 0, N_NODES * sizeof(float), s);
    count_edges<<<(N_EDGES + 255) / 256, 256, 0, s>>>(e_p_node, e_c_node, g_cp, g_cc);

    // ---- h0 = MLP_V(batch_token) ----
    gemm_plain<<<gemm_grid(N_NODES, H1), 256, 0, s>>>(
        batch_token, N_NODES, D, Vw1, H1, Vb1, g_hid, 0, nullptr, nullptr);
    gemm_plain<<<gemm_grid(N_NODES, D), 256, 0, s>>>(
        g_hid, N_NODES, H1, Vw2, D, Vb2, g_h, 0, nullptr, nullptr);

    // ---- edge features (computed once) ----
    size_t eh_threads = (size_t)N_EDGES * H1;
    edge_hidden<<<(unsigned)((eh_threads + 255) / 256), 256, 0, s>>>(e_p_ind, Ew1, Eb1, g_hid);
    gemm_plain<<<gemm_grid(N_EDGES, D), 256, 0, s>>>(
        g_hid, N_EDGES, H1, Ew2, D, Eb2, g_ep, 0, nullptr, nullptr);
    edge_hidden<<<(unsigned)((eh_threads + 255) / 256), 256, 0, s>>>(e_c_ind, Ew1, Eb1, g_hid);
    gemm_plain<<<gemm_grid(N_EDGES, D), 256, 0, s>>>(
        g_hid, N_EDGES, H1, Ew2, D, Eb2, g_ec, 0, nullptr, nullptr);

    // ---- hops ----
    float* hin  = g_h;
    float* hout = g_h2;
    for (int hop = 0; hop < 3; hop++) {
        cudaMemsetAsync(g_sp, 0, (size_t)N_NODES * D * sizeof(float), s);
        cudaMemsetAsync(g_sc, 0, (size_t)N_NODES * D * sizeof(float), s);

        // s_p = segsum_p( MLP_P(cat[hc, hp, edge_p]) )
        gemm_cat3<<<gemm_grid(N_EDGES, H1), 256, 0, s>>>(
            hin, e_c_node, hin, e_p_node, g_ep, N_EDGES, Pw1, Pb1, g_hid);
        gemm_plain<<<gemm_grid(N_EDGES, D), 256, 0, s>>>(
            g_hid, N_EDGES, H1, Pw2, D, Pb2, g_sp, 1, e_p_node, nullptr);

        // s_c = segsum_c( MLP_C(cat[hp, hc, edge_c]) )
        gemm_cat3<<<gemm_grid(N_EDGES, H1), 256, 0, s>>>(
            hin, e_p_node, hin, e_c_node, g_ec, N_EDGES, Cw1, Cb1, g_hid);
        gemm_plain<<<gemm_grid(N_EDGES, D), 256, 0, s>>>(
            g_hid, N_EDGES, H1, Cw2, D, Cb2, g_sc, 1, e_c_node, nullptr);

        finalize_s<<<(N_NODES * D + 255) / 256, 256, 0, s>>>(
            g_sp, g_sc, g_cp, g_cc, p_mask, c_mask, start_tok, end_tok);

        // h = relu(h + MLP_A(cat[h, s_p, s_c]))
        gemm_cat3<<<gemm_grid(N_NODES, H1), 256, 0, s>>>(
            hin, nullptr, g_sp, nullptr, g_sc, N_NODES, Aw1, Ab1, g_hid);
        float* hdst = (hop == 2) ? (float*)d_out : hout;
        gemm_plain<<<gemm_grid(N_NODES, D), 256, 0, s>>>(
            g_hid, N_NODES, H1, Aw2, D, Ab2, hdst, 2, nullptr, hin);

        float* tmp = hin;
        hin  = hdst;
        hout = tmp;
    }
}

// round 2
// speedup vs baseline: 2.9248x; 2.9248x over previous
#include <cuda_runtime.h>
#include <cstdint>
#include <cstddef>

#define N_NODES 50000
#define N_EDGES 500000
#define D 128
#define H1 256

// ---------------- scratch (static device globals; no allocation) ----------------
__device__ float d_h  [N_NODES * D];
__device__ float d_h2 [N_NODES * D];
__device__ float d_hid[(size_t)N_EDGES * H1];      // hidden scratch (512 MB)
__device__ float d_ep [(size_t)N_EDGES * D];       // edge_p features (computed once)
__device__ float d_ec [(size_t)N_EDGES * D];       // edge_c features
__device__ float d_sp [N_NODES * D];
__device__ float d_sc [N_NODES * D];
__device__ float d_cp [N_NODES];
__device__ float d_cc [N_NODES];

// ---------------- helpers ----------------
__device__ __forceinline__ uint32_t f2tf32(float v) {
    uint32_t r;
    asm("cvt.rna.tf32.f32 %0, %1;" : "=r"(r) : "f"(v));
    return r;
}

__device__ __forceinline__ void mma_tf32(float c[4],
                                         uint32_t a0, uint32_t a1, uint32_t a2, uint32_t a3,
                                         uint32_t b0, uint32_t b1) {
    asm volatile(
        "mma.sync.aligned.m16n8k8.row.col.f32.tf32.tf32.f32 "
        "{%0,%1,%2,%3}, {%4,%5,%6,%7}, {%8,%9}, {%0,%1,%2,%3};"
        : "+f"(c[0]), "+f"(c[1]), "+f"(c[2]), "+f"(c[3])
        : "r"(a0), "r"(a1), "r"(a2), "r"(a3), "r"(b0), "r"(b1));
}

// ---------------- unified tf32 tensor-core GEMM ----------------
// out[M,Nn] = epilogue( A[M,K] @ W[K,Nn] + bias )
// A loader:
//   0 DIRECT : A(r,k) = A[r*K + k]
//   1 CAT3   : K=384; seg s = k/128: s0/i0, s1/i1, s2 (idx==null -> identity)
//   2 RANK1  : A(r,k) = relu(ind[r]*w1[k] + b1[k])   (fused edge-MLP layer 1)
// epilogue mode:
//   0 : out = relu(v)
//   1 : atomicAdd(&out[sidx[r]*Nn+c], relu(v))
//   2 : out = relu(res[r*Nn+c] + relu(v))
// Block tile: 128(M) x 64(N), BK=32, 256 threads (8 warps, 4x2 warp grid, 32x32/warp)
__global__ __launch_bounds__(256) void gemm_tc(
    const float* __restrict__ A,
    const float* __restrict__ s0, const int* __restrict__ i0,
    const float* __restrict__ s1, const int* __restrict__ i1,
    const float* __restrict__ s2,
    const float* __restrict__ rk_ind, const float* __restrict__ rk_w1,
    const float* __restrict__ rk_b1,
    int M, int K,
    const float* __restrict__ W, int Nn,
    const float* __restrict__ bias,
    float* __restrict__ out,
    int loader, int mode, const int* __restrict__ sidx,
    const float* __restrict__ res)
{
    __shared__ float As[128][36];   // [m][k], pad 4 -> frag bank = (lane + k) % 32, conflict-free
    __shared__ float Bs[32][72];    // [k][n], pad 8 -> frag bank = 8*(lane&3)+(lane>>2), conflict-free

    const int tid  = threadIdx.x;
    const int lane = tid & 31;
    const int wid  = tid >> 5;
    const int wm   = (wid & 3) * 32;   // warp M offset in tile
    const int wn   = (wid >> 2) * 32;  // warp N offset in tile
    const int bm   = blockIdx.y * 128;
    const int bn   = blockIdx.x * 64;

    float acc[2][4][4] = {};

    for (int k0 = 0; k0 < K; k0 += 32) {
        // ---- stage A tile [128 x 32] ----
        {
            const float* src = A;
            const int*   idx = nullptr;
            int koff = k0;
            if (loader == 1) {
                int seg = k0 >> 7;
                src  = (seg == 0) ? s0 : (seg == 1) ? s1 : s2;
                idx  = (seg == 0) ? i0 : (seg == 1) ? i1 : nullptr;
                koff = k0 & 127;
            }
            const int kq = (tid & 7) * 4;
#pragma unroll
            for (int it = 0; it < 4; ++it) {
                int r  = it * 32 + (tid >> 3);
                int gr = bm + r;
                float4 v = make_float4(0.f, 0.f, 0.f, 0.f);
                if (gr < M) {
                    if (loader == 2) {
                        float ind = __ldg(rk_ind + gr);
                        float4 w  = *(const float4*)(rk_w1 + k0 + kq);
                        float4 b  = *(const float4*)(rk_b1 + k0 + kq);
                        v.x = fmaxf(fmaf(ind, w.x, b.x), 0.f);
                        v.y = fmaxf(fmaf(ind, w.y, b.y), 0.f);
                        v.z = fmaxf(fmaf(ind, w.z, b.z), 0.f);
                        v.w = fmaxf(fmaf(ind, w.w, b.w), 0.f);
                    } else if (loader == 1) {
                        int rr = idx ? idx[gr] : gr;
                        v = *(const float4*)(src + (size_t)rr * 128 + koff + kq);
                    } else {
                        v = *(const float4*)(src + (size_t)gr * K + k0 + kq);
                    }
                }
                float4 t;
                t.x = __uint_as_float(f2tf32(v.x));
                t.y = __uint_as_float(f2tf32(v.y));
                t.z = __uint_as_float(f2tf32(v.z));
                t.w = __uint_as_float(f2tf32(v.w));
                *(float4*)&As[r][kq] = t;
            }
        }
        // ---- stage B tile [32 x 64] ----
        {
            const int nq = (tid & 15) * 4;
#pragma unroll
            for (int it = 0; it < 2; ++it) {
                int kk = it * 16 + (tid >> 4);
                float4 v = *(const float4*)(W + (size_t)(k0 + kk) * Nn + bn + nq);
                float4 t;
                t.x = __uint_as_float(f2tf32(v.x));
                t.y = __uint_as_float(f2tf32(v.y));
                t.z = __uint_as_float(f2tf32(v.z));
                t.w = __uint_as_float(f2tf32(v.w));
                *(float4*)&Bs[kk][nq] = t;
            }
        }
        __syncthreads();

        // ---- compute: 4 k-steps of 8 ----
#pragma unroll
        for (int ks = 0; ks < 4; ++ks) {
            const int k = ks * 8;
            uint32_t a[2][4];
#pragma unroll
            for (int mi = 0; mi < 2; ++mi) {
                int row = wm + mi * 16 + (lane >> 2);
                int kc  = k + (lane & 3);
                a[mi][0] = __float_as_uint(As[row    ][kc    ]);
                a[mi][1] = __float_as_uint(As[row + 8][kc    ]);
                a[mi][2] = __float_as_uint(As[row    ][kc + 4]);
                a[mi][3] = __float_as_uint(As[row + 8][kc + 4]);
            }
#pragma unroll
            for (int ni = 0; ni < 4; ++ni) {
                int nc = wn + ni * 8 + (lane >> 2);
                int kc = k + (lane & 3);
                uint32_t b0 = __float_as_uint(Bs[kc    ][nc]);
                uint32_t b1 = __float_as_uint(Bs[kc + 4][nc]);
#pragma unroll
                for (int mi = 0; mi < 2; ++mi)
                    mma_tf32(acc[mi][ni], a[mi][0], a[mi][1], a[mi][2], a[mi][3], b0, b1);
            }
        }
        __syncthreads();
    }

    // ---- epilogue ----
#pragma unroll
    for (int mi = 0; mi < 2; ++mi) {
        int r0 = bm + wm + mi * 16 + (lane >> 2);
        int r1 = r0 + 8;
#pragma unroll
        for (int ni = 0; ni < 4; ++ni) {
            int c0 = bn + wn + ni * 8 + (lane & 3) * 2;
            int c1 = c0 + 1;
            float bz0 = bias[c0], bz1 = bias[c1];
            float v00 = fmaxf(acc[mi][ni][0] + bz0, 0.f);
            float v01 = fmaxf(acc[mi][ni][1] + bz1, 0.f);
            float v10 = fmaxf(acc[mi][ni][2] + bz0, 0.f);
            float v11 = fmaxf(acc[mi][ni][3] + bz1, 0.f);
            if (mode == 0) {
                if (r0 < M) {
                    out[(size_t)r0 * Nn + c0] = v00;
                    out[(size_t)r0 * Nn + c1] = v01;
                }
                if (r1 < M) {
                    out[(size_t)r1 * Nn + c0] = v10;
                    out[(size_t)r1 * Nn + c1] = v11;
                }
            } else if (mode == 1) {
                if (r0 < M) {
                    size_t b = (size_t)sidx[r0] * Nn;
                    atomicAdd(&out[b + c0], v00);
                    atomicAdd(&out[b + c1], v01);
                }
                if (r1 < M) {
                    size_t b = (size_t)sidx[r1] * Nn;
                    atomicAdd(&out[b + c0], v10);
                    atomicAdd(&out[b + c1], v11);
                }
            } else {
                if (r0 < M) {
                    size_t b = (size_t)r0 * Nn;
                    out[b + c0] = fmaxf(res[b + c0] + v00, 0.f);
                    out[b + c1] = fmaxf(res[b + c1] + v01, 0.f);
                }
                if (r1 < M) {
                    size_t b = (size_t)r1 * Nn;
                    out[b + c0] = fmaxf(res[b + c0] + v10, 0.f);
                    out[b + c1] = fmaxf(res[b + c1] + v11, 0.f);
                }
            }
        }
    }
}

// ---------------- small elementwise kernels ----------------
__global__ void count_edges(const int* __restrict__ pn, const int* __restrict__ cn,
                            float* __restrict__ cp, float* __restrict__ cc)
{
    int e = blockIdx.x * blockDim.x + threadIdx.x;
    if (e < N_EDGES) {
        atomicAdd(&cp[pn[e]], 1.f);
        atomicAdd(&cc[cn[e]], 1.f);
    }
}

__global__ void finalize_s(float* __restrict__ sp, float* __restrict__ sc,
                           const float* __restrict__ cp, const float* __restrict__ cc,
                           const float* __restrict__ pm, const float* __restrict__ cm,
                           const float* __restrict__ st, const float* __restrict__ et)
{
    int i = blockIdx.x * blockDim.x + threadIdx.x;
    if (i >= N_NODES * D) return;
    int n = i >> 7, d = i & 127;
    sp[i] = sp[i] / fmaxf(cp[n], 1.f) + pm[n] * st[d];
    sc[i] = sc[i] / fmaxf(cc[n], 1.f) + cm[n] * et[d];
}

// ---------------- host ----------------
static inline dim3 tc_grid(int M, int Nn) { return dim3(Nn / 64, (M + 127) / 128); }

extern "C" void kernel_launch(void* const* d_in, const int* in_sizes, int n_in,
                              void* d_out, int out_size)
{
    (void)in_sizes; (void)n_in; (void)out_size;
    const float* batch_token = (const float*)d_in[0];
    const int*   e_p_node    = (const int*)  d_in[1];
    const int*   e_c_node    = (const int*)  d_in[2];
    const float* e_p_ind     = (const float*)d_in[3];
    const float* e_c_ind     = (const float*)d_in[4];
    const float* p_mask      = (const float*)d_in[5];
    const float* c_mask      = (const float*)d_in[6];
    const float* start_tok   = (const float*)d_in[7];
    const float* end_tok     = (const float*)d_in[8];
    const float* Wt[20];
    for (int i = 0; i < 20; i++) Wt[i] = (const float*)d_in[9 + i];
    const float *Vw1=Wt[0],*Vb1=Wt[1],*Vw2=Wt[2],*Vb2=Wt[3];
    const float *Ew1=Wt[4],*Eb1=Wt[5],*Ew2=Wt[6],*Eb2=Wt[7];
    const float *Pw1=Wt[8],*Pb1=Wt[9],*Pw2=Wt[10],*Pb2=Wt[11];
    const float *Cw1=Wt[12],*Cb1=Wt[13],*Cw2=Wt[14],*Cb2=Wt[15];
    const float *Aw1=Wt[16],*Ab1=Wt[17],*Aw2=Wt[18],*Ab2=Wt[19];

    float *g_h, *g_h2, *g_hid, *g_ep, *g_ec, *g_sp, *g_sc, *g_cp, *g_cc;
    cudaGetSymbolAddress((void**)&g_h,   d_h);
    cudaGetSymbolAddress((void**)&g_h2,  d_h2);
    cudaGetSymbolAddress((void**)&g_hid, d_hid);
    cudaGetSymbolAddress((void**)&g_ep,  d_ep);
    cudaGetSymbolAddress((void**)&g_ec,  d_ec);
    cudaGetSymbolAddress((void**)&g_sp,  d_sp);
    cudaGetSymbolAddress((void**)&g_sc,  d_sc);
    cudaGetSymbolAddress((void**)&g_cp,  d_cp);
    cudaGetSymbolAddress((void**)&g_cc,  d_cc);

    cudaStream_t s = 0;

    // ---- edge counts ----
    cudaMemsetAsync(g_cp, 0, N_NODES * sizeof(float), s);
    cudaMemsetAsync(g_cc, 0, N_NODES * sizeof(float), s);
    count_edges<<<(N_EDGES + 255) / 256, 256, 0, s>>>(e_p_node, e_c_node, g_cp, g_cc);

    // ---- h0 = MLP_V(batch_token) ----
    gemm_tc<<<tc_grid(N_NODES, H1), 256, 0, s>>>(
        batch_token, nullptr, nullptr, nullptr, nullptr, nullptr,
        nullptr, nullptr, nullptr,
        N_NODES, D, Vw1, H1, Vb1, g_hid, 0, 0, nullptr, nullptr);
    gemm_tc<<<tc_grid(N_NODES, D), 256, 0, s>>>(
        g_hid, nullptr, nullptr, nullptr, nullptr, nullptr,
        nullptr, nullptr, nullptr,
        N_NODES, H1, Vw2, D, Vb2, g_h, 0, 0, nullptr, nullptr);

    // ---- edge features (layer1 fused into A-loader via RANK1) ----
    gemm_tc<<<tc_grid(N_EDGES, D), 256, 0, s>>>(
        nullptr, nullptr, nullptr, nullptr, nullptr, nullptr,
        e_p_ind, Ew1, Eb1,
        N_EDGES, H1, Ew2, D, Eb2, g_ep, 2, 0, nullptr, nullptr);
    gemm_tc<<<tc_grid(N_EDGES, D), 256, 0, s>>>(
        nullptr, nullptr, nullptr, nullptr, nullptr, nullptr,
        e_c_ind, Ew1, Eb1,
        N_EDGES, H1, Ew2, D, Eb2, g_ec, 2, 0, nullptr, nullptr);

    // ---- hops ----
    float* hin  = g_h;
    float* hout = g_h2;
    for (int hop = 0; hop < 3; hop++) {
        cudaMemsetAsync(g_sp, 0, (size_t)N_NODES * D * sizeof(float), s);
        cudaMemsetAsync(g_sc, 0, (size_t)N_NODES * D * sizeof(float), s);

        // s_p = segsum_p( MLP_P(cat[hc, hp, edge_p]) )
        gemm_tc<<<tc_grid(N_EDGES, H1), 256, 0, s>>>(
            nullptr, hin, e_c_node, hin, e_p_node, g_ep,
            nullptr, nullptr, nullptr,
            N_EDGES, 3 * D, Pw1, H1, Pb1, g_hid, 1, 0, nullptr, nullptr);
        gemm_tc<<<tc_grid(N_EDGES, D), 256, 0, s>>>(
            g_hid, nullptr, nullptr, nullptr, nullptr, nullptr,
            nullptr, nullptr, nullptr,
            N_EDGES, H1, Pw2, D, Pb2, g_sp, 0, 1, e_p_node, nullptr);

        // s_c = segsum_c( MLP_C(cat[hp, hc, edge_c]) )
        gemm_tc<<<tc_grid(N_EDGES, H1), 256, 0, s>>>(
            nullptr, hin, e_p_node, hin, e_c_node, g_ec,
            nullptr, nullptr, nullptr,
            N_EDGES, 3 * D, Cw1, H1, Cb1, g_hid, 1, 0, nullptr, nullptr);
        gemm_tc<<<tc_grid(N_EDGES, D), 256, 0, s>>>(
            g_hid, nullptr, nullptr, nullptr, nullptr, nullptr,
            nullptr, nullptr, nullptr,
            N_EDGES, H1, Cw2, D, Cb2, g_sc, 0, 1, e_c_node, nullptr);

        finalize_s<<<(N_NODES * D + 255) / 256, 256, 0, s>>>(
            g_sp, g_sc, g_cp, g_cc, p_mask, c_mask, start_tok, end_tok);

        // h = relu(h + MLP_A(cat[h, s_p, s_c]))
        gemm_tc<<<tc_grid(N_NODES, H1), 256, 0, s>>>(
            nullptr, hin, nullptr, g_sp, nullptr, g_sc,
            nullptr, nullptr, nullptr,
            N_NODES, 3 * D, Aw1, H1, Ab1, g_hid, 1, 0, nullptr, nullptr);
        float* hdst = (hop == 2) ? (float*)d_out : hout;
        gemm_tc<<<tc_grid(N_NODES, D), 256, 0, s>>>(
            g_hid, nullptr, nullptr, nullptr, nullptr, nullptr,
            nullptr, nullptr, nullptr,
            N_NODES, H1, Aw2, D, Ab2, hdst, 0, 2, nullptr, hin);

        float* tmp = hin;
        hin  = hdst;
        hout = tmp;
    }
}

// round 3
// speedup vs baseline: 4.2956x; 1.4687x over previous
#include <cuda_runtime.h>
#include <cstdint>
#include <cstddef>

#define N_NODES 50000
#define N_EDGES 500000
#define D 128
#define H1 256

#define BM 128
#define BN 64
#define BK 32
#define AS_LD 36
#define BS_LD 72
#define AS_SZ (BM * AS_LD)           // floats per A buffer
#define BS_SZ (BK * BS_LD)           // floats per B buffer
#define SMEM_FLOATS (2 * AS_SZ + 2 * BS_SZ)
#define SMEM_BYTES  (SMEM_FLOATS * 4)

// ---------------- scratch (static device globals; no allocation) ----------------
__device__ float d_h  [N_NODES * D];
__device__ float d_h2 [N_NODES * D];
__device__ float d_hid[(size_t)N_EDGES * H1];
__device__ float d_ep [(size_t)N_EDGES * D];
__device__ float d_ec [(size_t)N_EDGES * D];
__device__ float d_sp [N_NODES * D];
__device__ float d_sc [N_NODES * D];
__device__ float d_cp [N_NODES];
__device__ float d_cc [N_NODES];

// ---------------- helpers ----------------
__device__ __forceinline__ void mma_tf32(float c[4],
                                         uint32_t a0, uint32_t a1, uint32_t a2, uint32_t a3,
                                         uint32_t b0, uint32_t b1) {
    asm volatile(
        "mma.sync.aligned.m16n8k8.row.col.f32.tf32.tf32.f32 "
        "{%0,%1,%2,%3}, {%4,%5,%6,%7}, {%8,%9}, {%0,%1,%2,%3};"
        : "+f"(c[0]), "+f"(c[1]), "+f"(c[2]), "+f"(c[3])
        : "r"(a0), "r"(a1), "r"(a2), "r"(a3), "r"(b0), "r"(b1));
}

__device__ __forceinline__ void cp16(float* sm, const float* gm, bool pred) {
    uint32_t sa = (uint32_t)__cvta_generic_to_shared(sm);
    int sz = pred ? 16 : 0;
    asm volatile("cp.async.cg.shared.global [%0], [%1], 16, %2;\n"
                 :: "r"(sa), "l"(gm), "r"(sz));
}

// ---------------- unified tf32 tensor-core GEMM (cp.async double-buffered) ----
// loader: 0 DIRECT, 1 CAT3 (K=384, gathered), 2 RANK1 (fused edge-MLP layer1)
// mode:   0 relu-store, 1 atomic scatter-add of relu, 2 residual double-relu
__global__ __launch_bounds__(256) void gemm_tc(
    const float* __restrict__ A,
    const float* __restrict__ s0, const int* __restrict__ i0,
    const float* __restrict__ s1, const int* __restrict__ i1,
    const float* __restrict__ s2,
    const float* __restrict__ rk_ind, const float* __restrict__ rk_w1,
    const float* __restrict__ rk_b1,
    int M, int K,
    const float* __restrict__ W, int Nn,
    const float* __restrict__ bias,
    float* __restrict__ out,
    int loader, int mode, const int* __restrict__ sidx,
    const float* __restrict__ res)
{
    extern __shared__ float smem[];
    float* AsBase = smem;                  // 2 x [BM][AS_LD]
    float* BsBase = smem + 2 * AS_SZ;      // 2 x [BK][BS_LD]

    const int tid  = threadIdx.x;
    const int lane = tid & 31;
    const int wid  = tid >> 5;
    const int wm   = (wid & 3) * 32;
    const int wn   = (wid >> 2) * 32;
    const int bm   = blockIdx.y * BM;
    const int bn   = blockIdx.x * BN;

    // ---- per-thread A staging map (rows fixed for all k-tiles) ----
    const int akq = (tid & 7) * 4;         // k-offset within tile (float4)
    int  arow[4]; bool aval[4];
    int  rr0[4], rr1[4];
    float aind[4];
#pragma unroll
    for (int it = 0; it < 4; ++it) {
        int r  = it * 32 + (tid >> 3);
        int gr = bm + r;
        aval[it] = (gr < M);
        int g = aval[it] ? gr : 0;
        arow[it] = g;
        if (loader == 1) {
            rr0[it] = i0 ? i0[g] : g;
            rr1[it] = i1 ? i1[g] : g;
        } else if (loader == 2) {
            aind[it] = aval[it] ? __ldg(rk_ind + g) : 0.f;
        }
    }
    // ---- B staging map ----
    const int bnq = (tid & 15) * 4;
    const int bk0 = tid >> 4;              // rows bk0, bk0+16

    float acc[2][4][4] = {};
    const int KT = K / BK;

    // ---------------- pipeline ----------------
#define STAGE_A(k0, Ab)                                                          \
    do {                                                                         \
        if (loader == 2) {                                                       \
            float4 w  = *(const float4*)(rk_w1 + (k0) + akq);                    \
            float4 bb = *(const float4*)(rk_b1 + (k0) + akq);                    \
            _Pragma("unroll")                                                    \
            for (int it = 0; it < 4; ++it) {                                     \
                int r = it * 32 + (tid >> 3);                                    \
                float4 v;                                                        \
                v.x = fmaxf(fmaf(aind[it], w.x, bb.x), 0.f);                     \
                v.y = fmaxf(fmaf(aind[it], w.y, bb.y), 0.f);                     \
                v.z = fmaxf(fmaf(aind[it], w.z, bb.z), 0.f);                     \
                v.w = fmaxf(fmaf(aind[it], w.w, bb.w), 0.f);                     \
                *(float4*)&(Ab)[r * AS_LD + akq] = v;                            \
            }                                                                    \
        } else {                                                                 \
            _Pragma("unroll")                                                    \
            for (int it = 0; it < 4; ++it) {                                     \
                int r = it * 32 + (tid >> 3);                                    \
                const float* src;                                                \
                if (loader == 1) {                                               \
                    int seg  = (k0) >> 7;                                        \
                    int koff = ((k0) & 127) + akq;                               \
                    src = (seg == 0) ? s0 + (size_t)rr0[it] * 128 + koff         \
                        : (seg == 1) ? s1 + (size_t)rr1[it] * 128 + koff         \
                        :              s2 + (size_t)arow[it] * 128 + koff;       \
                } else {                                                         \
                    src = A + (size_t)arow[it] * K + (k0) + akq;                 \
                }                                                                \
                cp16(&(Ab)[r * AS_LD + akq], src, aval[it]);                     \
            }                                                                    \
        }                                                                        \
    } while (0)

#define STAGE_B(k0, Bb)                                                          \
    do {                                                                         \
        _Pragma("unroll")                                                        \
        for (int it = 0; it < 2; ++it) {                                         \
            int kk = it * 16 + bk0;                                              \
            cp16(&(Bb)[kk * BS_LD + bnq],                                        \
                 W + (size_t)((k0) + kk) * Nn + bn + bnq, true);                 \
        }                                                                        \
    } while (0)

    STAGE_A(0, AsBase);
    STAGE_B(0, BsBase);
    asm volatile("cp.async.commit_group;\n" ::: "memory");

    for (int t = 0; t < KT; ++t) {
        const int cur = t & 1, nxt = (t + 1) & 1;
        if (t + 1 < KT) {
            STAGE_A((t + 1) * BK, AsBase + nxt * AS_SZ);
            STAGE_B((t + 1) * BK, BsBase + nxt * BS_SZ);
        }
        asm volatile("cp.async.commit_group;\n" ::: "memory");
        asm volatile("cp.async.wait_group 1;\n" ::: "memory");
        __syncthreads();

        const float* Ab = AsBase + cur * AS_SZ;
        const float* Bb = BsBase + cur * BS_SZ;
#pragma unroll
        for (int ks = 0; ks < 4; ++ks) {
            const int k = ks * 8;
            uint32_t a[2][4];
#pragma unroll
            for (int mi = 0; mi < 2; ++mi) {
                int row = wm + mi * 16 + (lane >> 2);
                int kc  = k + (lane & 3);
                a[mi][0] = __float_as_uint(Ab[ row      * AS_LD + kc    ]);
                a[mi][1] = __float_as_uint(Ab[(row + 8) * AS_LD + kc    ]);
                a[mi][2] = __float_as_uint(Ab[ row      * AS_LD + kc + 4]);
                a[mi][3] = __float_as_uint(Ab[(row + 8) * AS_LD + kc + 4]);
            }
#pragma unroll
            for (int ni = 0; ni < 4; ++ni) {
                int nc = wn + ni * 8 + (lane >> 2);
                int kc = k + (lane & 3);
                uint32_t b0 = __float_as_uint(Bb[ kc      * BS_LD + nc]);
                uint32_t b1 = __float_as_uint(Bb[(kc + 4) * BS_LD + nc]);
#pragma unroll
                for (int mi = 0; mi < 2; ++mi)
                    mma_tf32(acc[mi][ni], a[mi][0], a[mi][1], a[mi][2], a[mi][3], b0, b1);
            }
        }
        __syncthreads();
    }

    // ---------------- epilogue ----------------
#pragma unroll
    for (int mi = 0; mi < 2; ++mi) {
        int r0 = bm + wm + mi * 16 + (lane >> 2);
        int r1 = r0 + 8;
#pragma unroll
        for (int ni = 0; ni < 4; ++ni) {
            int c0 = bn + wn + ni * 8 + (lane & 3) * 2;
            int c1 = c0 + 1;
            float bz0 = bias[c0], bz1 = bias[c1];
            float v00 = fmaxf(acc[mi][ni][0] + bz0, 0.f);
            float v01 = fmaxf(acc[mi][ni][1] + bz1, 0.f);
            float v10 = fmaxf(acc[mi][ni][2] + bz0, 0.f);
            float v11 = fmaxf(acc[mi][ni][3] + bz1, 0.f);
            if (mode == 0) {
                if (r0 < M) {
                    out[(size_t)r0 * Nn + c0] = v00;
                    out[(size_t)r0 * Nn + c1] = v01;
                }
                if (r1 < M) {
                    out[(size_t)r1 * Nn + c0] = v10;
                    out[(size_t)r1 * Nn + c1] = v11;
                }
            } else if (mode == 1) {
                if (r0 < M) {
                    size_t b = (size_t)sidx[r0] * Nn;
                    atomicAdd(&out[b + c0], v00);
                    atomicAdd(&out[b + c1], v01);
                }
                if (r1 < M) {
                    size_t b = (size_t)sidx[r1] * Nn;
                    atomicAdd(&out[b + c0], v10);
                    atomicAdd(&out[b + c1], v11);
                }
            } else {
                if (r0 < M) {
                    size_t b = (size_t)r0 * Nn;
                    out[b + c0] = fmaxf(res[b + c0] + v00, 0.f);
                    out[b + c1] = fmaxf(res[b + c1] + v01, 0.f);
                }
                if (r1 < M) {
                    size_t b = (size_t)r1 * Nn;
                    out[b + c0] = fmaxf(res[b + c0] + v10, 0.f);
                    out[b + c1] = fmaxf(res[b + c1] + v11, 0.f);
                }
            }
        }
    }
#undef STAGE_A
#undef STAGE_B
}

// ---------------- small elementwise kernels ----------------
__global__ void count_edges(const int* __restrict__ pn, const int* __restrict__ cn,
                            float* __restrict__ cp, float* __restrict__ cc)
{
    int e = blockIdx.x * blockDim.x + threadIdx.x;
    if (e < N_EDGES) {
        atomicAdd(&cp[pn[e]], 1.f);
        atomicAdd(&cc[cn[e]], 1.f);
    }
}

__global__ void finalize_s(float* __restrict__ sp, float* __restrict__ sc,
                           const float* __restrict__ cp, const float* __restrict__ cc,
                           const float* __restrict__ pm, const float* __restrict__ cm,
                           const float* __restrict__ st, const float* __restrict__ et)
{
    int i = blockIdx.x * blockDim.x + threadIdx.x;
    if (i >= N_NODES * D) return;
    int n = i >> 7, d = i & 127;
    sp[i] = sp[i] / fmaxf(cp[n], 1.f) + pm[n] * st[d];
    sc[i] = sc[i] / fmaxf(cc[n], 1.f) + cm[n] * et[d];
}

// ---------------- host ----------------
static inline dim3 tc_grid(int M, int Nn) { return dim3(Nn / BN, (M + BM - 1) / BM); }

extern "C" void kernel_launch(void* const* d_in, const int* in_sizes, int n_in,
                              void* d_out, int out_size)
{
    (void)in_sizes; (void)n_in; (void)out_size;
    const float* batch_token = (const float*)d_in[0];
    const int*   e_p_node    = (const int*)  d_in[1];
    const int*   e_c_node    = (const int*)  d_in[2];
    const float* e_p_ind     = (const float*)d_in[3];
    const float* e_c_ind     = (const float*)d_in[4];
    const float* p_mask      = (const float*)d_in[5];
    const float* c_mask      = (const float*)d_in[6];
    const float* start_tok   = (const float*)d_in[7];
    const float* end_tok     = (const float*)d_in[8];
    const float* Wt[20];
    for (int i = 0; i < 20; i++) Wt[i] = (const float*)d_in[9 + i];
    const float *Vw1=Wt[0],*Vb1=Wt[1],*Vw2=Wt[2],*Vb2=Wt[3];
    const float *Ew1=Wt[4],*Eb1=Wt[5],*Ew2=Wt[6],*Eb2=Wt[7];
    const float *Pw1=Wt[8],*Pb1=Wt[9],*Pw2=Wt[10],*Pb2=Wt[11];
    const float *Cw1=Wt[12],*Cb1=Wt[13],*Cw2=Wt[14],*Cb2=Wt[15];
    const float *Aw1=Wt[16],*Ab1=Wt[17],*Aw2=Wt[18],*Ab2=Wt[19];

    float *g_h, *g_h2, *g_hid, *g_ep, *g_ec, *g_sp, *g_sc, *g_cp, *g_cc;
    cudaGetSymbolAddress((void**)&g_h,   d_h);
    cudaGetSymbolAddress((void**)&g_h2,  d_h2);
    cudaGetSymbolAddress((void**)&g_hid, d_hid);
    cudaGetSymbolAddress((void**)&g_ep,  d_ep);
    cudaGetSymbolAddress((void**)&g_ec,  d_ec);
    cudaGetSymbolAddress((void**)&g_sp,  d_sp);
    cudaGetSymbolAddress((void**)&g_sc,  d_sc);
    cudaGetSymbolAddress((void**)&g_cp,  d_cp);
    cudaGetSymbolAddress((void**)&g_cc,  d_cc);

    cudaFuncSetAttribute(gemm_tc, cudaFuncAttributeMaxDynamicSharedMemorySize, SMEM_BYTES);

    cudaStream_t s = 0;
    const size_t SB = SMEM_BYTES;

    // ---- edge counts ----
    cudaMemsetAsync(g_cp, 0, N_NODES * sizeof(float), s);
    cudaMemsetAsync(g_cc, 0, N_NODES * sizeof(float), s);
    count_edges<<<(N_EDGES + 255) / 256, 256, 0, s>>>(e_p_node, e_c_node, g_cp, g_cc);

    // ---- h0 = MLP_V(batch_token) ----
    gemm_tc<<<tc_grid(N_NODES, H1), 256, SB, s>>>(
        batch_token, nullptr, nullptr, nullptr, nullptr, nullptr,
        nullptr, nullptr, nullptr,
        N_NODES, D, Vw1, H1, Vb1, g_hid, 0, 0, nullptr, nullptr);
    gemm_tc<<<tc_grid(N_NODES, D), 256, SB, s>>>(
        g_hid, nullptr, nullptr, nullptr, nullptr, nullptr,
        nullptr, nullptr, nullptr,
        N_NODES, H1, Vw2, D, Vb2, g_h, 0, 0, nullptr, nullptr);

    // ---- edge features (layer1 fused via RANK1 loader) ----
    gemm_tc<<<tc_grid(N_EDGES, D), 256, SB, s>>>(
        nullptr, nullptr, nullptr, nullptr, nullptr, nullptr,
        e_p_ind, Ew1, Eb1,
        N_EDGES, H1, Ew2, D, Eb2, g_ep, 2, 0, nullptr, nullptr);
    gemm_tc<<<tc_grid(N_EDGES, D), 256, SB, s>>>(
        nullptr, nullptr, nullptr, nullptr, nullptr, nullptr,
        e_c_ind, Ew1, Eb1,
        N_EDGES, H1, Ew2, D, Eb2, g_ec, 2, 0, nullptr, nullptr);

    // ---- hops ----
    float* hin  = g_h;
    float* hout = g_h2;
    for (int hop = 0; hop < 3; hop++) {
        cudaMemsetAsync(g_sp, 0, (size_t)N_NODES * D * sizeof(float), s);
        cudaMemsetAsync(g_sc, 0, (size_t)N_NODES * D * sizeof(float), s);

        gemm_tc<<<tc_grid(N_EDGES, H1), 256, SB, s>>>(
            nullptr, hin, e_c_node, hin, e_p_node, g_ep,
            nullptr, nullptr, nullptr,
            N_EDGES, 3 * D, Pw1, H1, Pb1, g_hid, 1, 0, nullptr, nullptr);
        gemm_tc<<<tc_grid(N_EDGES, D), 256, SB, s>>>(
            g_hid, nullptr, nullptr, nullptr, nullptr, nullptr,
            nullptr, nullptr, nullptr,
            N_EDGES, H1, Pw2, D, Pb2, g_sp, 0, 1, e_p_node, nullptr);

        gemm_tc<<<tc_grid(N_EDGES, H1), 256, SB, s>>>(
            nullptr, hin, e_p_node, hin, e_c_node, g_ec,
            nullptr, nullptr, nullptr,
            N_EDGES, 3 * D, Cw1, H1, Cb1, g_hid, 1, 0, nullptr, nullptr);
        gemm_tc<<<tc_grid(N_EDGES, D), 256, SB, s>>>(
            g_hid, nullptr, nullptr, nullptr, nullptr, nullptr,
            nullptr, nullptr, nullptr,
            N_EDGES, H1, Cw2, D, Cb2, g_sc, 0, 1, e_c_node, nullptr);

        finalize_s<<<(N_NODES * D + 255) / 256, 256, 0, s>>>(
            g_sp, g_sc, g_cp, g_cc, p_mask, c_mask, start_tok, end_tok);

        gemm_tc<<<tc_grid(N_NODES, H1), 256, SB, s>>>(
            nullptr, hin, nullptr, g_sp, nullptr, g_sc,
            nullptr, nullptr, nullptr,
            N_NODES, 3 * D, Aw1, H1, Ab1, g_hid, 1, 0, nullptr, nullptr);
        float* hdst = (hop == 2) ? (float*)d_out : hout;
        gemm_tc<<<tc_grid(N_NODES, D), 256, SB, s>>>(
            g_hid, nullptr, nullptr, nullptr, nullptr, nullptr,
            nullptr, nullptr, nullptr,
            N_NODES, H1, Aw2, D, Ab2, hdst, 0, 2, nullptr, hin);

        float* tmp = hin;
        hin  = hdst;
        hout = tmp;
    }
}